// round 1
// baseline (speedup 1.0000x reference)
#include <cuda_runtime.h>

// Scratch for the tiny reduced matrix M_re[2][100] (device global: no allocation).
__device__ float g_M[200];

// Stage 1: M_re[k,a] = sum_ij ( P_re[i,j]*A_real[k,i,j,a] - P_im[i,j]*A_imag[k,i,j,a] )
// P_re = psi_r psi_r^T + psi_i psi_i^T ; P_im = psi_r psi_i^T - psi_i psi_r^T
// One block, 256 threads; tid < 200 owns one (k,a) pair. 40k float reads total.
__global__ void compute_M_kernel(const float* __restrict__ A_real,
                                 const float* __restrict__ A_imag,
                                 const float* __restrict__ psi_real,
                                 const float* __restrict__ psi_imag) {
    __shared__ float pr[10], pi[10];
    if (threadIdx.x < 10) {
        pr[threadIdx.x] = psi_real[threadIdx.x];
        pi[threadIdx.x] = psi_imag[threadIdx.x];
    }
    __syncthreads();

    int tid = threadIdx.x;
    if (tid < 200) {
        int k = tid / 100;
        int a = tid - k * 100;
        float acc = 0.0f;
        #pragma unroll
        for (int i = 0; i < 10; i++) {
            #pragma unroll
            for (int j = 0; j < 10; j++) {
                float Pre = pr[i] * pr[j] + pi[i] * pi[j];
                float Pim = pr[i] * pi[j] - pi[i] * pr[j];
                int idx = ((k * 10 + i) * 10 + j) * 100 + a;
                acc = fmaf(Pre, A_real[idx], acc);
                acc = fmaf(-Pim, A_imag[idx], acc);
            }
        }
        g_M[tid] = acc;
    }
}

// Stage 2: out[t, k] = sum_a x[t,a] * M[k,a]. Warp-per-row.
// Lanes 0..24 each load one float4 (coalesced 400B per warp), dual dot-product,
// butterfly reduce, lane 0 stores float2 {out[t,0], out[t,1]}.
__global__ void __launch_bounds__(256) gemv_kernel(const float* __restrict__ x,
                                                   float* __restrict__ out,
                                                   int batch) {
    __shared__ float sM[200];
    if (threadIdx.x < 200) sM[threadIdx.x] = g_M[threadIdx.x];
    __syncthreads();

    int gwarp = (blockIdx.x * blockDim.x + threadIdx.x) >> 5;
    int lane  = threadIdx.x & 31;
    if (gwarp >= batch) return;

    float s0 = 0.0f, s1 = 0.0f;
    if (lane < 25) {
        const float4* row = reinterpret_cast<const float4*>(x + (size_t)gwarp * 100);
        float4 v = row[lane];
        int a = lane * 4;
        s0 = v.x * sM[a]       + v.y * sM[a + 1]       + v.z * sM[a + 2]       + v.w * sM[a + 3];
        s1 = v.x * sM[100 + a] + v.y * sM[100 + a + 1] + v.z * sM[100 + a + 2] + v.w * sM[100 + a + 3];
    }

    #pragma unroll
    for (int off = 16; off > 0; off >>= 1) {
        s0 += __shfl_xor_sync(0xffffffff, s0, off);
        s1 += __shfl_xor_sync(0xffffffff, s1, off);
    }

    if (lane == 0) {
        float2 r = make_float2(s0, s1);
        *reinterpret_cast<float2*>(out + (size_t)gwarp * 2) = r;
    }
}

extern "C" void kernel_launch(void* const* d_in, const int* in_sizes, int n_in,
                              void* d_out, int out_size) {
    const float* x        = (const float*)d_in[0];  // [BATCH, 100]
    const float* A_real   = (const float*)d_in[1];  // [2,10,10,100]
    const float* A_imag   = (const float*)d_in[2];  // [2,10,10,100]
    const float* psi_real = (const float*)d_in[3];  // [10]
    const float* psi_imag = (const float*)d_in[4];  // [10]
    float* out = (float*)d_out;                     // [BATCH, 2]

    int batch = in_sizes[0] / 100;

    compute_M_kernel<<<1, 256>>>(A_real, A_imag, psi_real, psi_imag);

    int warps_per_block = 256 / 32;               // 8 rows per block
    int blocks = (batch + warps_per_block - 1) / warps_per_block;
    gemv_kernel<<<blocks, 256>>>(x, out, batch);
}

// round 2
// speedup vs baseline: 1.2347x; 1.2347x over previous
#include <cuda_runtime.h>

// Reduced matrix M_re[2][100], 16B-aligned for float4 access. No allocation.
__device__ __align__(16) float g_M[200];

// Stage 1: M_re[k,a] = sum_ij ( P_re[i,j]*A_real[k,i,j,a] - P_im[i,j]*A_imag[k,i,j,a] )
// 1 block, 256 threads; tid < 200 owns one (k,a). Coalesced over 'a', MLP=200/thread.
__global__ void compute_M_kernel(const float* __restrict__ A_real,
                                 const float* __restrict__ A_imag,
                                 const float* __restrict__ psi_real,
                                 const float* __restrict__ psi_imag) {
    __shared__ float pr[10], pi[10];
    if (threadIdx.x < 10) {
        pr[threadIdx.x] = psi_real[threadIdx.x];
        pi[threadIdx.x] = psi_imag[threadIdx.x];
    }
    __syncthreads();

    int tid = threadIdx.x;
    if (tid < 200) {
        int k = tid / 100;
        int a = tid - k * 100;
        float acc = 0.0f;
        #pragma unroll
        for (int i = 0; i < 10; i++) {
            #pragma unroll
            for (int j = 0; j < 10; j++) {
                float Pre = pr[i] * pr[j] + pi[i] * pi[j];
                float Pim = pr[i] * pi[j] - pi[i] * pr[j];
                int idx = ((k * 10 + i) * 10 + j) * 100 + a;
                acc = fmaf(Pre, A_real[idx], acc);
                acc = fmaf(-Pim, A_imag[idx], acc);
            }
        }
        g_M[tid] = acc;
    }
}

// Stage 2: out[t,k] = sum_a x[t,a] * M[k,a].
// Tile of 120 rows staged into smem with coalesced float4 LDG (every lane active),
// then thread-per-row dual dot product from smem. Row stride 100 floats makes the
// LDS.128 quarter-warp phases bank-conflict-free (4t mod 32 all distinct). M rows
// read as broadcast LDS.128 (no-penalty). No shuffles, no per-warp masked loads.
#define TILE_ROWS 120
#define BLOCK_T   128

__global__ void __launch_bounds__(BLOCK_T) gemv_kernel(const float4* __restrict__ x4,
                                                       float2* __restrict__ out,
                                                       int batch) {
    __shared__ float4 sx[TILE_ROWS * 25];   // 48000 B
    __shared__ float4 sM4[50];              // M[0][:] in 0..24, M[1][:] in 25..49

    int tid  = threadIdx.x;
    int row0 = blockIdx.x * TILE_ROWS;
    int rows = batch - row0;
    if (rows > TILE_ROWS) rows = TILE_ROWS;

    if (tid < 50) sM4[tid] = reinterpret_cast<const float4*>(g_M)[tid];

    // Phase 1: coalesced staging of the tile (rows*25 float4 = up to 3000).
    int n4 = rows * 25;
    const float4* src = x4 + (size_t)row0 * 25;
    for (int i = tid; i < n4; i += BLOCK_T) sx[i] = src[i];
    __syncthreads();

    // Phase 2: thread t reduces row t.
    if (tid < rows) {
        const float4* xr = &sx[tid * 25];
        float s0 = 0.0f, s1 = 0.0f;
        #pragma unroll
        for (int i = 0; i < 25; i++) {
            float4 v  = xr[i];
            float4 m0 = sM4[i];
            float4 m1 = sM4[25 + i];
            s0 = fmaf(v.x, m0.x, s0); s0 = fmaf(v.y, m0.y, s0);
            s0 = fmaf(v.z, m0.z, s0); s0 = fmaf(v.w, m0.w, s0);
            s1 = fmaf(v.x, m1.x, s1); s1 = fmaf(v.y, m1.y, s1);
            s1 = fmaf(v.z, m1.z, s1); s1 = fmaf(v.w, m1.w, s1);
        }
        out[row0 + tid] = make_float2(s0, s1);
    }
}

extern "C" void kernel_launch(void* const* d_in, const int* in_sizes, int n_in,
                              void* d_out, int out_size) {
    const float* x        = (const float*)d_in[0];  // [BATCH, 100]
    const float* A_real   = (const float*)d_in[1];  // [2,10,10,100]
    const float* A_imag   = (const float*)d_in[2];  // [2,10,10,100]
    const float* psi_real = (const float*)d_in[3];  // [10]
    const float* psi_imag = (const float*)d_in[4];  // [10]

    int batch = in_sizes[0] / 100;

    compute_M_kernel<<<1, 256>>>(A_real, A_imag, psi_real, psi_imag);

    int blocks = (batch + TILE_ROWS - 1) / TILE_ROWS;
    gemv_kernel<<<blocks, BLOCK_T>>>(reinterpret_cast<const float4*>(x),
                                     reinterpret_cast<float2*>(d_out), batch);
}

// round 3
// speedup vs baseline: 1.8369x; 1.4877x over previous
#include <cuda_runtime.h>
#include <cstdint>

// Partial reductions: g_Mpart[k*1000 + i*100 + a], summed over j by stage 1.
// Final M[k][a] = sum_i g_Mpart[k][i][a], formed per-block in stage 2.
__device__ __align__(16) float g_Mpart[2000];

// ---------------- Stage 1: 20 blocks, one per (k,i) pair ----------------
__global__ void compute_Mpart_kernel(const float* __restrict__ A_real,
                                     const float* __restrict__ A_imag,
                                     const float* __restrict__ psi_real,
                                     const float* __restrict__ psi_imag) {
    __shared__ float pr[10], pi[10];
    if (threadIdx.x < 10) {
        pr[threadIdx.x] = psi_real[threadIdx.x];
        pi[threadIdx.x] = psi_imag[threadIdx.x];
    }
    __syncthreads();

    int ki = blockIdx.x;          // 0..19 -> (k, i)
    int k  = ki / 10;
    int i  = ki - k * 10;
    int a  = threadIdx.x;
    if (a >= 100) return;

    float acc = 0.0f;
    #pragma unroll
    for (int j = 0; j < 10; j++) {
        float Pre = pr[i] * pr[j] + pi[i] * pi[j];
        float Pim = pr[i] * pi[j] - pi[i] * pr[j];
        int idx = ((k * 10 + i) * 10 + j) * 100 + a;
        acc = fmaf(Pre, A_real[idx], acc);
        acc = fmaf(-Pim, A_imag[idx], acc);
    }
    g_Mpart[k * 1000 + i * 100 + a] = acc;
}

// ---------------- Stage 2: pipelined streaming GEMV ----------------
// out[t,k] = sum_a x[t,a] * M[k,a];  x streamed through smem with cp.async
// double buffering so DRAM reads overlap compute. TILE=256 rows, 2 stages,
// 1 block/SM (204.8KB dynamic smem), grid-stride over tiles.
#define TILE     256
#define BLOCK_T  128
#define F4_PER_TILE (TILE * 25)                  // 6400 float4
#define SMEM_BYTES  (2 * F4_PER_TILE * 16)       // 204800

__device__ __forceinline__ void cp_async16(void* smem_dst, const void* gsrc) {
    uint32_t d = (uint32_t)__cvta_generic_to_shared(smem_dst);
    asm volatile("cp.async.cg.shared.global [%0], [%1], 16;\n" :: "r"(d), "l"(gsrc));
}

__global__ void __launch_bounds__(BLOCK_T) gemv_kernel(const float4* __restrict__ x4,
                                                       float2* __restrict__ out,
                                                       int batch, int ntiles) {
    extern __shared__ float4 sx[];               // [2][F4_PER_TILE]
    __shared__ __align__(16) float sMf[200];

    int tid = threadIdx.x;

    // Build M in smem: sum the 10 stage-1 partials per (k,a).
    for (int j = tid; j < 200; j += BLOCK_T) {
        int k = j / 100, a = j - k * 100;
        float acc = 0.0f;
        #pragma unroll
        for (int i = 0; i < 10; i++) acc += g_Mpart[k * 1000 + i * 100 + a];
        sMf[j] = acc;
    }
    const float4* sM4 = reinterpret_cast<const float4*>(sMf);   // [50]

    int nblk = gridDim.x;
    int first = blockIdx.x;
    if (first >= ntiles) { __syncthreads(); return; }

    // Prefetch one tile into stage s.
    auto prefetch = [&](int t, int s) {
        const float4* src = x4 + (size_t)t * F4_PER_TILE;
        float4* dst = sx + s * F4_PER_TILE;
        int limit = batch * 25 - t * F4_PER_TILE;    // valid f4 in this tile
        #pragma unroll 5
        for (int i = tid; i < F4_PER_TILE; i += BLOCK_T)
            if (i < limit) cp_async16(dst + i, src + i);
        asm volatile("cp.async.commit_group;\n");
    };

    prefetch(first, 0);

    int cnt = 0;
    for (int t = first; t < ntiles; t += nblk, cnt++) {
        int s = cnt & 1;
        int tn = t + nblk;
        bool more = (tn < ntiles);
        if (more) {
            prefetch(tn, s ^ 1);
            asm volatile("cp.async.wait_group 1;\n");
        } else {
            asm volatile("cp.async.wait_group 0;\n");
        }
        __syncthreads();

        // Compute: thread handles rows (tid) and (tid+128) of this tile.
        const float4* ra = sx + s * F4_PER_TILE + tid * 25;
        const float4* rb = ra + 128 * 25;
        float s0a = 0.f, s1a = 0.f, s0b = 0.f, s1b = 0.f;
        #pragma unroll
        for (int i = 0; i < 25; i++) {
            float4 m0 = sM4[i];
            float4 m1 = sM4[25 + i];
            float4 va = ra[i];
            float4 vb = rb[i];
            s0a = fmaf(va.x, m0.x, s0a); s0a = fmaf(va.y, m0.y, s0a);
            s0a = fmaf(va.z, m0.z, s0a); s0a = fmaf(va.w, m0.w, s0a);
            s1a = fmaf(va.x, m1.x, s1a); s1a = fmaf(va.y, m1.y, s1a);
            s1a = fmaf(va.z, m1.z, s1a); s1a = fmaf(va.w, m1.w, s1a);
            s0b = fmaf(vb.x, m0.x, s0b); s0b = fmaf(vb.y, m0.y, s0b);
            s0b = fmaf(vb.z, m0.z, s0b); s0b = fmaf(vb.w, m0.w, s0b);
            s1b = fmaf(vb.x, m1.x, s1b); s1b = fmaf(vb.y, m1.y, s1b);
            s1b = fmaf(vb.z, m1.z, s1b); s1b = fmaf(vb.w, m1.w, s1b);
        }
        int row = t * TILE + tid;
        if (row < batch)       out[row]       = make_float2(s0a, s1a);
        if (row + 128 < batch) out[row + 128] = make_float2(s0b, s1b);
        __syncthreads();   // stage s free for the prefetch issued at t+2*nblk
    }
}

extern "C" void kernel_launch(void* const* d_in, const int* in_sizes, int n_in,
                              void* d_out, int out_size) {
    const float* x        = (const float*)d_in[0];  // [BATCH, 100]
    const float* A_real   = (const float*)d_in[1];  // [2,10,10,100]
    const float* A_imag   = (const float*)d_in[2];  // [2,10,10,100]
    const float* psi_real = (const float*)d_in[3];  // [10]
    const float* psi_imag = (const float*)d_in[4];  // [10]

    int batch  = in_sizes[0] / 100;
    int ntiles = (batch + TILE - 1) / TILE;

    static bool attr_done = false;
    if (!attr_done) {
        cudaFuncSetAttribute(gemv_kernel,
                             cudaFuncAttributeMaxDynamicSharedMemorySize, SMEM_BYTES);
        attr_done = true;
    }

    compute_Mpart_kernel<<<20, 128>>>(A_real, A_imag, psi_real, psi_imag);

    int nblk = 148;
    if (nblk > ntiles) nblk = ntiles;
    gemv_kernel<<<nblk, BLOCK_T, SMEM_BYTES>>>(reinterpret_cast<const float4*>(x),
                                               reinterpret_cast<float2*>(d_out),
                                               batch, ntiles);
}